// round 11
// baseline (speedup 1.0000x reference)
#include <cuda_runtime.h>
#include <cstdint>
#include <cstddef>

#define NTOK 4096
#define DMODEL 1024
#define VOCAB 50257

// Scratch (allocation-free contract)
__device__ float g_x [(size_t)NTOK * DMODEL];
__device__ float g_q [(size_t)NTOK * DMODEL];
__device__ float g_k [(size_t)NTOK * DMODEL];
__device__ float g_vt[(size_t)NTOK * DMODEL];   // V^T: [DMODEL, NTOK]
__device__ float g_s [(size_t)NTOK * NTOK];
__device__ float g_o [(size_t)NTOK * DMODEL];

// round-to-nearest tf32 (unbiased; result exactly representable in fp32)
__device__ __forceinline__ float tf32r(float x) {
    uint32_t u;
    asm("cvt.rna.tf32.f32 %0, %1;" : "=r"(u) : "f"(x));
    return __uint_as_float(u);
}
__device__ __forceinline__ float4 tf32r4(float4 v) {
    return make_float4(tf32r(v.x), tf32r(v.y), tf32r(v.z), tf32r(v.w));
}
__device__ __forceinline__ float4 sub4(float4 a, float4 b) {
    return make_float4(a.x - b.x, a.y - b.y, a.z - b.z, a.w - b.w);
}

__device__ __forceinline__ void mma16n8k8(float* d, const float* a, const float* b) {
    asm volatile(
        "mma.sync.aligned.m16n8k8.row.col.f32.tf32.tf32.f32 "
        "{%0,%1,%2,%3}, {%4,%5,%6,%7}, {%8,%9}, {%0,%1,%2,%3};"
        : "+f"(d[0]), "+f"(d[1]), "+f"(d[2]), "+f"(d[3])
        : "r"(__float_as_uint(a[0])), "r"(__float_as_uint(a[1])),
          "r"(__float_as_uint(a[2])), "r"(__float_as_uint(a[3])),
          "r"(__float_as_uint(b[0])), "r"(__float_as_uint(b[1])));
}

// ---------------------------------------------------------------------------
// Core GEMM body (device function):  C[M,N] = alpha*A@B^T (+bias), from (m0,n0)
// ---------------------------------------------------------------------------
template <bool SPLIT, bool TRANS_OUT>
__device__ __forceinline__ void gemm_body(
    const float* __restrict__ A, const float* __restrict__ B,
    const float* __restrict__ bias, float* __restrict__ C,
    int M, int N, int K, float alpha, int ldc, int m0, int n0, float* smem)
{
    constexpr int BM = 128, SST = 20;
    constexpr int TILE = BM * SST;
    constexpr int NB = SPLIT ? 4 : 2;

    const int tid  = threadIdx.x;
    const int wid  = tid >> 5;
    const int lane = tid & 31;
    const int g    = lane >> 2;
    const int tg   = lane & 3;

    const int wm = (wid & 1) * 64;
    const int wn = (wid >> 1) * 32;

    const int lrow0 = tid >> 2;
    const int lcol  = (tid & 3) * 4;

    float acc[4][4][4];
#pragma unroll
    for (int mf = 0; mf < 4; ++mf)
#pragma unroll
        for (int nf = 0; nf < 4; ++nf)
#pragma unroll
            for (int r = 0; r < 4; ++r) acc[mf][nf][r] = 0.0f;

    const int nchunks = K / 16;
    float4 ra[2], rb[2];

    // ---- prologue: load chunk 0 ----
#pragma unroll
    for (int r = 0; r < 2; ++r) {
        const int row = lrow0 + r * 64;
        ra[r] = *reinterpret_cast<const float4*>(A + (size_t)(m0 + row) * K + lcol);
        const int gn = n0 + row;
        rb[r] = (gn < N) ? *reinterpret_cast<const float4*>(B + (size_t)gn * K + lcol)
                         : make_float4(0.f, 0.f, 0.f, 0.f);
    }
    {
        float* Ah = smem;
        float* Bh = Ah + TILE;
        float* Al = Bh + TILE;
        float* Bl = Al + TILE;
#pragma unroll
        for (int r = 0; r < 2; ++r) {
            const int row = lrow0 + r * 64;
            float4 ah = tf32r4(ra[r]), bh = tf32r4(rb[r]);
            *reinterpret_cast<float4*>(Ah + row * SST + lcol) = ah;
            *reinterpret_cast<float4*>(Bh + row * SST + lcol) = bh;
            if (SPLIT) {
                *reinterpret_cast<float4*>(Al + row * SST + lcol) = tf32r4(sub4(ra[r], ah));
                *reinterpret_cast<float4*>(Bl + row * SST + lcol) = tf32r4(sub4(rb[r], bh));
            }
        }
    }
    __syncthreads();

    for (int i = 1; i <= nchunks; ++i) {
        if (i < nchunks) {
            const int k0 = i * 16;
#pragma unroll
            for (int r = 0; r < 2; ++r) {
                const int row = lrow0 + r * 64;
                ra[r] = *reinterpret_cast<const float4*>(A + (size_t)(m0 + row) * K + k0 + lcol);
                const int gn = n0 + row;
                rb[r] = (gn < N) ? *reinterpret_cast<const float4*>(B + (size_t)gn * K + k0 + lcol)
                                 : make_float4(0.f, 0.f, 0.f, 0.f);
            }
        }

        // ---- compute chunk i-1; fragments loaded once per k-step ----
        {
            float* st = smem + ((i - 1) & 1) * (NB * TILE);
            float* Ah = st;
            float* Bh = Ah + TILE;
            float* Al = Bh + TILE;
            float* Bl = Al + TILE;
#pragma unroll
            for (int ks = 0; ks < 2; ++ks) {
                const int kc = ks * 8 + tg;
                float ahf[4][4], bhf[4][2];
                float alf[4][4], blf[4][2];
#pragma unroll
                for (int mf = 0; mf < 4; ++mf) {
                    const int ar = wm + mf * 16 + g;
                    ahf[mf][0] = Ah[ar * SST + kc];
                    ahf[mf][1] = Ah[(ar + 8) * SST + kc];
                    ahf[mf][2] = Ah[ar * SST + kc + 4];
                    ahf[mf][3] = Ah[(ar + 8) * SST + kc + 4];
                    if (SPLIT) {
                        alf[mf][0] = Al[ar * SST + kc];
                        alf[mf][1] = Al[(ar + 8) * SST + kc];
                        alf[mf][2] = Al[ar * SST + kc + 4];
                        alf[mf][3] = Al[(ar + 8) * SST + kc + 4];
                    }
                }
#pragma unroll
                for (int nf = 0; nf < 4; ++nf) {
                    const int br = wn + nf * 8 + g;
                    bhf[nf][0] = Bh[br * SST + kc];
                    bhf[nf][1] = Bh[br * SST + kc + 4];
                    if (SPLIT) {
                        blf[nf][0] = Bl[br * SST + kc];
                        blf[nf][1] = Bl[br * SST + kc + 4];
                    }
                }
#pragma unroll
                for (int nf = 0; nf < 4; ++nf)
#pragma unroll
                    for (int mf = 0; mf < 4; ++mf)
                        mma16n8k8(acc[mf][nf], ahf[mf], bhf[nf]);
                if (SPLIT) {
#pragma unroll
                    for (int nf = 0; nf < 4; ++nf)
#pragma unroll
                        for (int mf = 0; mf < 4; ++mf)
                            mma16n8k8(acc[mf][nf], ahf[mf], blf[nf]);
#pragma unroll
                    for (int nf = 0; nf < 4; ++nf)
#pragma unroll
                        for (int mf = 0; mf < 4; ++mf)
                            mma16n8k8(acc[mf][nf], alf[mf], bhf[nf]);
                }
            }
        }

        if (i < nchunks) {
            float* st = smem + (i & 1) * (NB * TILE);
            float* Ah = st;
            float* Bh = Ah + TILE;
            float* Al = Bh + TILE;
            float* Bl = Al + TILE;
#pragma unroll
            for (int r = 0; r < 2; ++r) {
                const int row = lrow0 + r * 64;
                float4 ah = tf32r4(ra[r]), bh = tf32r4(rb[r]);
                *reinterpret_cast<float4*>(Ah + row * SST + lcol) = ah;
                *reinterpret_cast<float4*>(Bh + row * SST + lcol) = bh;
                if (SPLIT) {
                    *reinterpret_cast<float4*>(Al + row * SST + lcol) = tf32r4(sub4(ra[r], ah));
                    *reinterpret_cast<float4*>(Bl + row * SST + lcol) = tf32r4(sub4(rb[r], bh));
                }
            }
            __syncthreads();
        }
    }

    // ---- epilogue (scalar stores: ldc may be odd, e.g. VOCAB=50257) ----
#pragma unroll
    for (int mf = 0; mf < 4; ++mf) {
#pragma unroll
        for (int half = 0; half < 2; ++half) {
            const int gm = m0 + wm + mf * 16 + g + half * 8;
#pragma unroll
            for (int nf = 0; nf < 4; ++nf) {
                const int gn = n0 + wn + nf * 8 + tg * 2;
                float v0 = acc[mf][nf][half * 2 + 0] * alpha;
                float v1 = acc[mf][nf][half * 2 + 1] * alpha;
                if (bias) {
                    if (gn < N)     v0 += bias[gn];
                    if (gn + 1 < N) v1 += bias[gn + 1];
                }
                if (TRANS_OUT) {
                    if (gn < N)     C[(size_t)gn * ldc + gm] = v0;
                    if (gn + 1 < N) C[(size_t)(gn + 1) * ldc + gm] = v1;
                } else {
                    if (gn < N)     C[(size_t)gm * ldc + gn]     = v0;
                    if (gn + 1 < N) C[(size_t)gm * ldc + gn + 1] = v1;
                }
            }
        }
    }
}

// ---------------------------------------------------------------------------
// 2D-grid GEMM (n on x, m on y), optional causal tile skip
// ---------------------------------------------------------------------------
template <bool SPLIT, bool TRANS_OUT>
__global__ void __launch_bounds__(256, 1)
gemm_mma(const float* __restrict__ A, const float* __restrict__ B,
         const float* __restrict__ bias, float* __restrict__ C,
         int M, int N, int K, float alpha, int ldc, int causal)
{
    extern __shared__ float smem[];
    const int m0 = blockIdx.y * 128;
    const int n0 = blockIdx.x * 128;
    if (causal && n0 > m0 + 127) return;
    gemm_body<SPLIT, TRANS_OUT>(A, B, bias, C, M, N, K, alpha, ldc, m0, n0, smem);
}

// ---------------------------------------------------------------------------
// Grouped-swizzle GEMM (1D grid): groups of GROUP_M m-blocks, n fastest inside
// a group -> bounded B-tile reuse through L2 + clustered writes.
// occupancy 2 (regs<=128): 1-pass only.
// ---------------------------------------------------------------------------
template <bool SPLIT, int GROUP_M>
__global__ void __launch_bounds__(256, 2)
gemm_mma_grouped(const float* __restrict__ A, const float* __restrict__ B,
                 const float* __restrict__ bias, float* __restrict__ C,
                 int M, int N, int K, float alpha, int ldc)
{
    extern __shared__ float smem[];
    const int nbm = M / 128;
    const int nbn = (N + 127) / 128;
    const int bid = blockIdx.x;

    const int per_group  = GROUP_M * nbn;
    const int group      = bid / per_group;
    const int in_group   = bid % per_group;
    const int gm_blocks  = min(GROUP_M, nbm - group * GROUP_M);
    const int bm         = group * GROUP_M + in_group % gm_blocks;
    const int bn         = in_group / gm_blocks;

    gemm_body<SPLIT, false>(A, B, bias, C, M, N, K, alpha, ldc,
                            bm * 128, bn * 128, smem);
}

// ---------------------------------------------------------------------------
// Embedding gather
// ---------------------------------------------------------------------------
__global__ void gather_kernel(const int* __restrict__ tokens,
                              const float* __restrict__ E,
                              float* __restrict__ x) {
    int row = blockIdx.x;
    int t = tokens[row];
    const float4* src = reinterpret_cast<const float4*>(E + (size_t)t * DMODEL);
    float4* dst = reinterpret_cast<float4*>(x + (size_t)row * DMODEL);
    dst[threadIdx.x] = src[threadIdx.x];
}

// ---------------------------------------------------------------------------
// Causal row softmax in place
// ---------------------------------------------------------------------------
__global__ void softmax_causal_kernel(float* __restrict__ S) {
    const int row = blockIdx.x;
    float* s = S + (size_t)row * NTOK;
    const int len = row + 1;
    __shared__ float red[256];
    const int t = threadIdx.x;

    float m = -1e30f;
    for (int j = t; j < len; j += 256) m = fmaxf(m, s[j]);
    red[t] = m;
    __syncthreads();
#pragma unroll
    for (int st = 128; st > 0; st >>= 1) {
        if (t < st) red[t] = fmaxf(red[t], red[t + st]);
        __syncthreads();
    }
    m = red[0];
    __syncthreads();

    float sum = 0.0f;
    for (int j = t; j < len; j += 256) {
        const float e = expf(s[j] - m);
        s[j] = e;
        sum += e;
    }
    red[t] = sum;
    __syncthreads();
#pragma unroll
    for (int st = 128; st > 0; st >>= 1) {
        if (t < st) red[t] += red[t + st];
        __syncthreads();
    }
    const float inv = 1.0f / red[0];
    __syncthreads();

    for (int j = t; j < len; j += 256) s[j] *= inv;
    for (int j = len + t; j < NTOK; j += 256) s[j] = 0.0f;   // dense-GEMM tail
}

// ---------------------------------------------------------------------------
// Launch
// ---------------------------------------------------------------------------
extern "C" void kernel_launch(void* const* d_in, const int* in_sizes, int n_in,
                              void* d_out, int out_size) {
    const int*   tokens = (const int*)d_in[0];
    const float* E  = (const float*)d_in[1];
    const float* Wq = (const float*)d_in[2];
    const float* bq = (const float*)d_in[3];
    const float* Wk = (const float*)d_in[4];
    const float* bk = (const float*)d_in[5];
    const float* Wv = (const float*)d_in[6];
    const float* bv = (const float*)d_in[7];
    const float* Wp = (const float*)d_in[8];
    const float* bp = (const float*)d_in[9];
    float* out = (float*)d_out;

    float *x, *q, *k, *vt, *s, *o;
    cudaGetSymbolAddress((void**)&x,  g_x);
    cudaGetSymbolAddress((void**)&q,  g_q);
    cudaGetSymbolAddress((void**)&k,  g_k);
    cudaGetSymbolAddress((void**)&vt, g_vt);
    cudaGetSymbolAddress((void**)&s,  g_s);
    cudaGetSymbolAddress((void**)&o,  g_o);

    constexpr int SMEM_SPLIT = 2 * 4 * 128 * 20 * 4;   // 81920 B
    constexpr int SMEM_1P    = 2 * 2 * 128 * 20 * 4;   // 40960 B
    cudaFuncSetAttribute(gemm_mma<true, false>, cudaFuncAttributeMaxDynamicSharedMemorySize, SMEM_SPLIT);
    cudaFuncSetAttribute(gemm_mma<true, true >, cudaFuncAttributeMaxDynamicSharedMemorySize, SMEM_SPLIT);
    cudaFuncSetAttribute(gemm_mma_grouped<false, 16>, cudaFuncAttributeMaxDynamicSharedMemorySize, SMEM_1P);

    const float inv_sqrt_d = 1.0f / 32.0f;

    gather_kernel<<<NTOK, 256>>>(tokens, E, x);

    // Q/K = x @ W^T + b ; V written transposed for the AV GEMM
    dim3 g1(DMODEL / 128, NTOK / 128);
    gemm_mma<true, false><<<g1, 256, SMEM_SPLIT>>>(x, Wq, bq, q,  NTOK, DMODEL, DMODEL, 1.0f, DMODEL, 0);
    gemm_mma<true, false><<<g1, 256, SMEM_SPLIT>>>(x, Wk, bk, k,  NTOK, DMODEL, DMODEL, 1.0f, DMODEL, 0);
    gemm_mma<true, true ><<<g1, 256, SMEM_SPLIT>>>(x, Wv, bv, vt, NTOK, DMODEL, DMODEL, 1.0f, NTOK,   0);

    // S = Q @ K^T / sqrt(d)  (skip fully-masked tiles)
    dim3 g2(NTOK / 128, NTOK / 128);
    gemm_mma<true, false><<<g2, 256, SMEM_SPLIT>>>(q, k, nullptr, s, NTOK, NTOK, DMODEL, inv_sqrt_d, NTOK, 1);

    softmax_causal_kernel<<<NTOK, 256>>>(s);

    // O = A @ V  (B = V^T, K-major)
    gemm_mma<true, false><<<g1, 256, SMEM_SPLIT>>>(s, vt, nullptr, o, NTOK, DMODEL, NTOK, 1.0f, DMODEL, 0);

    // logits = O @ Wp^T + bp  (1-pass rna-tf32, grouped swizzle GROUP_M=16, occ=2)
    const int nbm = NTOK / 128;                 // 32
    const int nbn = (VOCAB + 127) / 128;        // 393
    gemm_mma_grouped<false, 16><<<nbm * nbn, 256, SMEM_1P>>>(
        o, Wp, bp, out, NTOK, VOCAB, DMODEL, 1.0f, VOCAB);
}

// round 12
// speedup vs baseline: 1.0001x; 1.0001x over previous
#include <cuda_runtime.h>
#include <cstdint>
#include <cstddef>

#define NTOK 4096
#define DMODEL 1024
#define VOCAB 50257

// Scratch (allocation-free contract)
__device__ float g_x [(size_t)NTOK * DMODEL];
__device__ float g_q [(size_t)NTOK * DMODEL];
__device__ float g_k [(size_t)NTOK * DMODEL];
__device__ float g_vt[(size_t)NTOK * DMODEL];   // V^T: [DMODEL, NTOK]
__device__ float g_s [(size_t)NTOK * NTOK];
__device__ float g_o [(size_t)NTOK * DMODEL];

// round-to-nearest tf32 (unbiased; result exactly representable in fp32)
__device__ __forceinline__ float tf32r(float x) {
    uint32_t u;
    asm("cvt.rna.tf32.f32 %0, %1;" : "=r"(u) : "f"(x));
    return __uint_as_float(u);
}
__device__ __forceinline__ float4 tf32r4(float4 v) {
    return make_float4(tf32r(v.x), tf32r(v.y), tf32r(v.z), tf32r(v.w));
}
__device__ __forceinline__ float4 sub4(float4 a, float4 b) {
    return make_float4(a.x - b.x, a.y - b.y, a.z - b.z, a.w - b.w);
}

__device__ __forceinline__ void mma16n8k8(float* d, const float* a, const float* b) {
    asm volatile(
        "mma.sync.aligned.m16n8k8.row.col.f32.tf32.tf32.f32 "
        "{%0,%1,%2,%3}, {%4,%5,%6,%7}, {%8,%9}, {%0,%1,%2,%3};"
        : "+f"(d[0]), "+f"(d[1]), "+f"(d[2]), "+f"(d[3])
        : "r"(__float_as_uint(a[0])), "r"(__float_as_uint(a[1])),
          "r"(__float_as_uint(a[2])), "r"(__float_as_uint(a[3])),
          "r"(__float_as_uint(b[0])), "r"(__float_as_uint(b[1])));
}

// ---------------------------------------------------------------------------
// Core GEMM body (device function):  C[M,N] = alpha*A@B^T (+bias), from (m0,n0)
// ---------------------------------------------------------------------------
template <bool SPLIT, bool TRANS_OUT>
__device__ __forceinline__ void gemm_body(
    const float* __restrict__ A, const float* __restrict__ B,
    const float* __restrict__ bias, float* __restrict__ C,
    int M, int N, int K, float alpha, int ldc, int m0, int n0, float* smem)
{
    constexpr int BM = 128, SST = 20;
    constexpr int TILE = BM * SST;
    constexpr int NB = SPLIT ? 4 : 2;

    const int tid  = threadIdx.x;
    const int wid  = tid >> 5;
    const int lane = tid & 31;
    const int g    = lane >> 2;
    const int tg   = lane & 3;

    const int wm = (wid & 1) * 64;
    const int wn = (wid >> 1) * 32;

    const int lrow0 = tid >> 2;
    const int lcol  = (tid & 3) * 4;

    float acc[4][4][4];
#pragma unroll
    for (int mf = 0; mf < 4; ++mf)
#pragma unroll
        for (int nf = 0; nf < 4; ++nf)
#pragma unroll
            for (int r = 0; r < 4; ++r) acc[mf][nf][r] = 0.0f;

    const int nchunks = K / 16;
    float4 ra[2], rb[2];

    // ---- prologue: load chunk 0 ----
#pragma unroll
    for (int r = 0; r < 2; ++r) {
        const int row = lrow0 + r * 64;
        ra[r] = *reinterpret_cast<const float4*>(A + (size_t)(m0 + row) * K + lcol);
        const int gn = n0 + row;
        rb[r] = (gn < N) ? *reinterpret_cast<const float4*>(B + (size_t)gn * K + lcol)
                         : make_float4(0.f, 0.f, 0.f, 0.f);
    }
    {
        float* Ah = smem;
        float* Bh = Ah + TILE;
        float* Al = Bh + TILE;
        float* Bl = Al + TILE;
#pragma unroll
        for (int r = 0; r < 2; ++r) {
            const int row = lrow0 + r * 64;
            float4 ah = tf32r4(ra[r]), bh = tf32r4(rb[r]);
            *reinterpret_cast<float4*>(Ah + row * SST + lcol) = ah;
            *reinterpret_cast<float4*>(Bh + row * SST + lcol) = bh;
            if (SPLIT) {
                *reinterpret_cast<float4*>(Al + row * SST + lcol) = tf32r4(sub4(ra[r], ah));
                *reinterpret_cast<float4*>(Bl + row * SST + lcol) = tf32r4(sub4(rb[r], bh));
            }
        }
    }
    __syncthreads();

    for (int i = 1; i <= nchunks; ++i) {
        if (i < nchunks) {
            const int k0 = i * 16;
#pragma unroll
            for (int r = 0; r < 2; ++r) {
                const int row = lrow0 + r * 64;
                ra[r] = *reinterpret_cast<const float4*>(A + (size_t)(m0 + row) * K + k0 + lcol);
                const int gn = n0 + row;
                rb[r] = (gn < N) ? *reinterpret_cast<const float4*>(B + (size_t)gn * K + k0 + lcol)
                                 : make_float4(0.f, 0.f, 0.f, 0.f);
            }
        }

        // ---- compute chunk i-1; fragments loaded once per k-step ----
        {
            float* st = smem + ((i - 1) & 1) * (NB * TILE);
            float* Ah = st;
            float* Bh = Ah + TILE;
            float* Al = Bh + TILE;
            float* Bl = Al + TILE;
#pragma unroll
            for (int ks = 0; ks < 2; ++ks) {
                const int kc = ks * 8 + tg;
                float ahf[4][4], bhf[4][2];
                float alf[4][4], blf[4][2];
#pragma unroll
                for (int mf = 0; mf < 4; ++mf) {
                    const int ar = wm + mf * 16 + g;
                    ahf[mf][0] = Ah[ar * SST + kc];
                    ahf[mf][1] = Ah[(ar + 8) * SST + kc];
                    ahf[mf][2] = Ah[ar * SST + kc + 4];
                    ahf[mf][3] = Ah[(ar + 8) * SST + kc + 4];
                    if (SPLIT) {
                        alf[mf][0] = Al[ar * SST + kc];
                        alf[mf][1] = Al[(ar + 8) * SST + kc];
                        alf[mf][2] = Al[ar * SST + kc + 4];
                        alf[mf][3] = Al[(ar + 8) * SST + kc + 4];
                    }
                }
#pragma unroll
                for (int nf = 0; nf < 4; ++nf) {
                    const int br = wn + nf * 8 + g;
                    bhf[nf][0] = Bh[br * SST + kc];
                    bhf[nf][1] = Bh[br * SST + kc + 4];
                    if (SPLIT) {
                        blf[nf][0] = Bl[br * SST + kc];
                        blf[nf][1] = Bl[br * SST + kc + 4];
                    }
                }
#pragma unroll
                for (int nf = 0; nf < 4; ++nf)
#pragma unroll
                    for (int mf = 0; mf < 4; ++mf)
                        mma16n8k8(acc[mf][nf], ahf[mf], bhf[nf]);
                if (SPLIT) {
#pragma unroll
                    for (int nf = 0; nf < 4; ++nf)
#pragma unroll
                        for (int mf = 0; mf < 4; ++mf)
                            mma16n8k8(acc[mf][nf], ahf[mf], blf[nf]);
#pragma unroll
                    for (int nf = 0; nf < 4; ++nf)
#pragma unroll
                        for (int mf = 0; mf < 4; ++mf)
                            mma16n8k8(acc[mf][nf], alf[mf], bhf[nf]);
                }
            }
        }

        if (i < nchunks) {
            float* st = smem + (i & 1) * (NB * TILE);
            float* Ah = st;
            float* Bh = Ah + TILE;
            float* Al = Bh + TILE;
            float* Bl = Al + TILE;
#pragma unroll
            for (int r = 0; r < 2; ++r) {
                const int row = lrow0 + r * 64;
                float4 ah = tf32r4(ra[r]), bh = tf32r4(rb[r]);
                *reinterpret_cast<float4*>(Ah + row * SST + lcol) = ah;
                *reinterpret_cast<float4*>(Bh + row * SST + lcol) = bh;
                if (SPLIT) {
                    *reinterpret_cast<float4*>(Al + row * SST + lcol) = tf32r4(sub4(ra[r], ah));
                    *reinterpret_cast<float4*>(Bl + row * SST + lcol) = tf32r4(sub4(rb[r], bh));
                }
            }
            __syncthreads();
        }
    }

    // ---- epilogue (scalar stores: ldc may be odd, e.g. VOCAB=50257) ----
#pragma unroll
    for (int mf = 0; mf < 4; ++mf) {
#pragma unroll
        for (int half = 0; half < 2; ++half) {
            const int gm = m0 + wm + mf * 16 + g + half * 8;
#pragma unroll
            for (int nf = 0; nf < 4; ++nf) {
                const int gn = n0 + wn + nf * 8 + tg * 2;
                float v0 = acc[mf][nf][half * 2 + 0] * alpha;
                float v1 = acc[mf][nf][half * 2 + 1] * alpha;
                if (bias) {
                    if (gn < N)     v0 += bias[gn];
                    if (gn + 1 < N) v1 += bias[gn + 1];
                }
                if (TRANS_OUT) {
                    if (gn < N)     C[(size_t)gn * ldc + gm] = v0;
                    if (gn + 1 < N) C[(size_t)(gn + 1) * ldc + gm] = v1;
                } else {
                    if (gn < N)     C[(size_t)gm * ldc + gn]     = v0;
                    if (gn + 1 < N) C[(size_t)gm * ldc + gn + 1] = v1;
                }
            }
        }
    }
}

// ---------------------------------------------------------------------------
// 2D-grid GEMM (n on x, m on y), optional causal tile skip
// ---------------------------------------------------------------------------
template <bool SPLIT, bool TRANS_OUT>
__global__ void __launch_bounds__(256, 1)
gemm_mma(const float* __restrict__ A, const float* __restrict__ B,
         const float* __restrict__ bias, float* __restrict__ C,
         int M, int N, int K, float alpha, int ldc, int causal)
{
    extern __shared__ float smem[];
    const int m0 = blockIdx.y * 128;
    const int n0 = blockIdx.x * 128;
    if (causal && n0 > m0 + 127) return;
    gemm_body<SPLIT, TRANS_OUT>(A, B, bias, C, M, N, K, alpha, ldc, m0, n0, smem);
}

// ---------------------------------------------------------------------------
// Grouped-swizzle GEMM (1D grid): groups of GROUP_M m-blocks, n fastest inside
// a group -> bounded B-tile reuse through L2 + clustered writes.
// occupancy 2 (regs<=128): 1-pass only.
// ---------------------------------------------------------------------------
template <bool SPLIT, int GROUP_M>
__global__ void __launch_bounds__(256, 2)
gemm_mma_grouped(const float* __restrict__ A, const float* __restrict__ B,
                 const float* __restrict__ bias, float* __restrict__ C,
                 int M, int N, int K, float alpha, int ldc)
{
    extern __shared__ float smem[];
    const int nbm = M / 128;
    const int nbn = (N + 127) / 128;
    const int bid = blockIdx.x;

    const int per_group  = GROUP_M * nbn;
    const int group      = bid / per_group;
    const int in_group   = bid % per_group;
    const int gm_blocks  = min(GROUP_M, nbm - group * GROUP_M);
    const int bm         = group * GROUP_M + in_group % gm_blocks;
    const int bn         = in_group / gm_blocks;

    gemm_body<SPLIT, false>(A, B, bias, C, M, N, K, alpha, ldc,
                            bm * 128, bn * 128, smem);
}

// ---------------------------------------------------------------------------
// Embedding gather
// ---------------------------------------------------------------------------
__global__ void gather_kernel(const int* __restrict__ tokens,
                              const float* __restrict__ E,
                              float* __restrict__ x) {
    int row = blockIdx.x;
    int t = tokens[row];
    const float4* src = reinterpret_cast<const float4*>(E + (size_t)t * DMODEL);
    float4* dst = reinterpret_cast<float4*>(x + (size_t)row * DMODEL);
    dst[threadIdx.x] = src[threadIdx.x];
}

// ---------------------------------------------------------------------------
// Causal row softmax in place
// ---------------------------------------------------------------------------
__global__ void softmax_causal_kernel(float* __restrict__ S) {
    const int row = blockIdx.x;
    float* s = S + (size_t)row * NTOK;
    const int len = row + 1;
    __shared__ float red[256];
    const int t = threadIdx.x;

    float m = -1e30f;
    for (int j = t; j < len; j += 256) m = fmaxf(m, s[j]);
    red[t] = m;
    __syncthreads();
#pragma unroll
    for (int st = 128; st > 0; st >>= 1) {
        if (t < st) red[t] = fmaxf(red[t], red[t + st]);
        __syncthreads();
    }
    m = red[0];
    __syncthreads();

    float sum = 0.0f;
    for (int j = t; j < len; j += 256) {
        const float e = expf(s[j] - m);
        s[j] = e;
        sum += e;
    }
    red[t] = sum;
    __syncthreads();
#pragma unroll
    for (int st = 128; st > 0; st >>= 1) {
        if (t < st) red[t] += red[t + st];
        __syncthreads();
    }
    const float inv = 1.0f / red[0];
    __syncthreads();

    for (int j = t; j < len; j += 256) s[j] *= inv;
    for (int j = len + t; j < NTOK; j += 256) s[j] = 0.0f;   // dense-GEMM tail
}

// ---------------------------------------------------------------------------
// Launch
// ---------------------------------------------------------------------------
extern "C" void kernel_launch(void* const* d_in, const int* in_sizes, int n_in,
                              void* d_out, int out_size) {
    const int*   tokens = (const int*)d_in[0];
    const float* E  = (const float*)d_in[1];
    const float* Wq = (const float*)d_in[2];
    const float* bq = (const float*)d_in[3];
    const float* Wk = (const float*)d_in[4];
    const float* bk = (const float*)d_in[5];
    const float* Wv = (const float*)d_in[6];
    const float* bv = (const float*)d_in[7];
    const float* Wp = (const float*)d_in[8];
    const float* bp = (const float*)d_in[9];
    float* out = (float*)d_out;

    float *x, *q, *k, *vt, *s, *o;
    cudaGetSymbolAddress((void**)&x,  g_x);
    cudaGetSymbolAddress((void**)&q,  g_q);
    cudaGetSymbolAddress((void**)&k,  g_k);
    cudaGetSymbolAddress((void**)&vt, g_vt);
    cudaGetSymbolAddress((void**)&s,  g_s);
    cudaGetSymbolAddress((void**)&o,  g_o);

    constexpr int SMEM_SPLIT = 2 * 4 * 128 * 20 * 4;   // 81920 B
    constexpr int SMEM_1P    = 2 * 2 * 128 * 20 * 4;   // 40960 B
    cudaFuncSetAttribute(gemm_mma<true, false>, cudaFuncAttributeMaxDynamicSharedMemorySize, SMEM_SPLIT);
    cudaFuncSetAttribute(gemm_mma<true, true >, cudaFuncAttributeMaxDynamicSharedMemorySize, SMEM_SPLIT);
    cudaFuncSetAttribute(gemm_mma_grouped<false, 16>, cudaFuncAttributeMaxDynamicSharedMemorySize, SMEM_1P);

    const float inv_sqrt_d = 1.0f / 32.0f;

    gather_kernel<<<NTOK, 256>>>(tokens, E, x);

    // Q/K = x @ W^T + b ; V written transposed for the AV GEMM
    dim3 g1(DMODEL / 128, NTOK / 128);
    gemm_mma<true, false><<<g1, 256, SMEM_SPLIT>>>(x, Wq, bq, q,  NTOK, DMODEL, DMODEL, 1.0f, DMODEL, 0);
    gemm_mma<true, false><<<g1, 256, SMEM_SPLIT>>>(x, Wk, bk, k,  NTOK, DMODEL, DMODEL, 1.0f, DMODEL, 0);
    gemm_mma<true, true ><<<g1, 256, SMEM_SPLIT>>>(x, Wv, bv, vt, NTOK, DMODEL, DMODEL, 1.0f, NTOK,   0);

    // S = Q @ K^T / sqrt(d)  (skip fully-masked tiles)
    dim3 g2(NTOK / 128, NTOK / 128);
    gemm_mma<true, false><<<g2, 256, SMEM_SPLIT>>>(q, k, nullptr, s, NTOK, NTOK, DMODEL, inv_sqrt_d, NTOK, 1);

    softmax_causal_kernel<<<NTOK, 256>>>(s);

    // O = A @ V  (B = V^T, K-major)
    gemm_mma<true, false><<<g1, 256, SMEM_SPLIT>>>(s, vt, nullptr, o, NTOK, DMODEL, NTOK, 1.0f, DMODEL, 0);

    // logits = O @ Wp^T + bp  (1-pass rna-tf32, grouped swizzle GROUP_M=16, occ=2)
    const int nbm = NTOK / 128;                 // 32
    const int nbn = (VOCAB + 127) / 128;        // 393
    gemm_mma_grouped<false, 16><<<nbm * nbn, 256, SMEM_1P>>>(
        o, Wp, bp, out, NTOK, VOCAB, DMODEL, 1.0f, VOCAB);
}

// round 13
// speedup vs baseline: 1.0009x; 1.0007x over previous
#include <cuda_runtime.h>
#include <cstdint>
#include <cstddef>

#define NTOK 4096
#define DMODEL 1024
#define VOCAB 50257

// Scratch (allocation-free contract)
__device__ float g_x [(size_t)NTOK * DMODEL];
__device__ float g_q [(size_t)NTOK * DMODEL];
__device__ float g_k [(size_t)NTOK * DMODEL];
__device__ float g_vt[(size_t)NTOK * DMODEL];   // V^T: [DMODEL, NTOK]
__device__ float g_s [(size_t)NTOK * NTOK];
__device__ float g_o [(size_t)NTOK * DMODEL];

// round-to-nearest tf32 (unbiased; result exactly representable in fp32)
__device__ __forceinline__ float tf32r(float x) {
    uint32_t u;
    asm("cvt.rna.tf32.f32 %0, %1;" : "=r"(u) : "f"(x));
    return __uint_as_float(u);
}
__device__ __forceinline__ float4 tf32r4(float4 v) {
    return make_float4(tf32r(v.x), tf32r(v.y), tf32r(v.z), tf32r(v.w));
}
__device__ __forceinline__ float4 sub4(float4 a, float4 b) {
    return make_float4(a.x - b.x, a.y - b.y, a.z - b.z, a.w - b.w);
}

__device__ __forceinline__ void mma16n8k8(float* d, const float* a, const float* b) {
    asm volatile(
        "mma.sync.aligned.m16n8k8.row.col.f32.tf32.tf32.f32 "
        "{%0,%1,%2,%3}, {%4,%5,%6,%7}, {%8,%9}, {%0,%1,%2,%3};"
        : "+f"(d[0]), "+f"(d[1]), "+f"(d[2]), "+f"(d[3])
        : "r"(__float_as_uint(a[0])), "r"(__float_as_uint(a[1])),
          "r"(__float_as_uint(a[2])), "r"(__float_as_uint(a[3])),
          "r"(__float_as_uint(b[0])), "r"(__float_as_uint(b[1])));
}

// ---------------------------------------------------------------------------
// Core GEMM body (device function):  C[M,N] = alpha*A@B^T (+bias), from (m0,n0)
// ---------------------------------------------------------------------------
template <bool SPLIT, bool TRANS_OUT>
__device__ __forceinline__ void gemm_body(
    const float* __restrict__ A, const float* __restrict__ B,
    const float* __restrict__ bias, float* __restrict__ C,
    int M, int N, int K, float alpha, int ldc, int m0, int n0, float* smem)
{
    constexpr int BM = 128, SST = 20;
    constexpr int TILE = BM * SST;
    constexpr int NB = SPLIT ? 4 : 2;

    const int tid  = threadIdx.x;
    const int wid  = tid >> 5;
    const int lane = tid & 31;
    const int g    = lane >> 2;
    const int tg   = lane & 3;

    const int wm = (wid & 1) * 64;
    const int wn = (wid >> 1) * 32;

    const int lrow0 = tid >> 2;
    const int lcol  = (tid & 3) * 4;

    float acc[4][4][4];
#pragma unroll
    for (int mf = 0; mf < 4; ++mf)
#pragma unroll
        for (int nf = 0; nf < 4; ++nf)
#pragma unroll
            for (int r = 0; r < 4; ++r) acc[mf][nf][r] = 0.0f;

    const int nchunks = K / 16;
    float4 ra[2], rb[2];

    // ---- prologue: load chunk 0 ----
#pragma unroll
    for (int r = 0; r < 2; ++r) {
        const int row = lrow0 + r * 64;
        ra[r] = *reinterpret_cast<const float4*>(A + (size_t)(m0 + row) * K + lcol);
        const int gn = n0 + row;
        rb[r] = (gn < N) ? *reinterpret_cast<const float4*>(B + (size_t)gn * K + lcol)
                         : make_float4(0.f, 0.f, 0.f, 0.f);
    }
    {
        float* Ah = smem;
        float* Bh = Ah + TILE;
        float* Al = Bh + TILE;
        float* Bl = Al + TILE;
#pragma unroll
        for (int r = 0; r < 2; ++r) {
            const int row = lrow0 + r * 64;
            float4 ah = tf32r4(ra[r]), bh = tf32r4(rb[r]);
            *reinterpret_cast<float4*>(Ah + row * SST + lcol) = ah;
            *reinterpret_cast<float4*>(Bh + row * SST + lcol) = bh;
            if (SPLIT) {
                *reinterpret_cast<float4*>(Al + row * SST + lcol) = tf32r4(sub4(ra[r], ah));
                *reinterpret_cast<float4*>(Bl + row * SST + lcol) = tf32r4(sub4(rb[r], bh));
            }
        }
    }
    __syncthreads();

    for (int i = 1; i <= nchunks; ++i) {
        if (i < nchunks) {
            const int k0 = i * 16;
#pragma unroll
            for (int r = 0; r < 2; ++r) {
                const int row = lrow0 + r * 64;
                ra[r] = *reinterpret_cast<const float4*>(A + (size_t)(m0 + row) * K + k0 + lcol);
                const int gn = n0 + row;
                rb[r] = (gn < N) ? *reinterpret_cast<const float4*>(B + (size_t)gn * K + k0 + lcol)
                                 : make_float4(0.f, 0.f, 0.f, 0.f);
            }
        }

        // ---- compute chunk i-1; fragments loaded once per k-step ----
        {
            float* st = smem + ((i - 1) & 1) * (NB * TILE);
            float* Ah = st;
            float* Bh = Ah + TILE;
            float* Al = Bh + TILE;
            float* Bl = Al + TILE;
#pragma unroll
            for (int ks = 0; ks < 2; ++ks) {
                const int kc = ks * 8 + tg;
                float ahf[4][4], bhf[4][2];
                float alf[4][4], blf[4][2];
#pragma unroll
                for (int mf = 0; mf < 4; ++mf) {
                    const int ar = wm + mf * 16 + g;
                    ahf[mf][0] = Ah[ar * SST + kc];
                    ahf[mf][1] = Ah[(ar + 8) * SST + kc];
                    ahf[mf][2] = Ah[ar * SST + kc + 4];
                    ahf[mf][3] = Ah[(ar + 8) * SST + kc + 4];
                    if (SPLIT) {
                        alf[mf][0] = Al[ar * SST + kc];
                        alf[mf][1] = Al[(ar + 8) * SST + kc];
                        alf[mf][2] = Al[ar * SST + kc + 4];
                        alf[mf][3] = Al[(ar + 8) * SST + kc + 4];
                    }
                }
#pragma unroll
                for (int nf = 0; nf < 4; ++nf) {
                    const int br = wn + nf * 8 + g;
                    bhf[nf][0] = Bh[br * SST + kc];
                    bhf[nf][1] = Bh[br * SST + kc + 4];
                    if (SPLIT) {
                        blf[nf][0] = Bl[br * SST + kc];
                        blf[nf][1] = Bl[br * SST + kc + 4];
                    }
                }
#pragma unroll
                for (int nf = 0; nf < 4; ++nf)
#pragma unroll
                    for (int mf = 0; mf < 4; ++mf)
                        mma16n8k8(acc[mf][nf], ahf[mf], bhf[nf]);
                if (SPLIT) {
#pragma unroll
                    for (int nf = 0; nf < 4; ++nf)
#pragma unroll
                        for (int mf = 0; mf < 4; ++mf)
                            mma16n8k8(acc[mf][nf], ahf[mf], blf[nf]);
#pragma unroll
                    for (int nf = 0; nf < 4; ++nf)
#pragma unroll
                        for (int mf = 0; mf < 4; ++mf)
                            mma16n8k8(acc[mf][nf], alf[mf], bhf[nf]);
                }
            }
        }

        if (i < nchunks) {
            float* st = smem + (i & 1) * (NB * TILE);
            float* Ah = st;
            float* Bh = Ah + TILE;
            float* Al = Bh + TILE;
            float* Bl = Al + TILE;
#pragma unroll
            for (int r = 0; r < 2; ++r) {
                const int row = lrow0 + r * 64;
                float4 ah = tf32r4(ra[r]), bh = tf32r4(rb[r]);
                *reinterpret_cast<float4*>(Ah + row * SST + lcol) = ah;
                *reinterpret_cast<float4*>(Bh + row * SST + lcol) = bh;
                if (SPLIT) {
                    *reinterpret_cast<float4*>(Al + row * SST + lcol) = tf32r4(sub4(ra[r], ah));
                    *reinterpret_cast<float4*>(Bl + row * SST + lcol) = tf32r4(sub4(rb[r], bh));
                }
            }
            __syncthreads();
        }
    }

    // ---- epilogue (scalar stores: ldc may be odd, e.g. VOCAB=50257) ----
#pragma unroll
    for (int mf = 0; mf < 4; ++mf) {
#pragma unroll
        for (int half = 0; half < 2; ++half) {
            const int gm = m0 + wm + mf * 16 + g + half * 8;
#pragma unroll
            for (int nf = 0; nf < 4; ++nf) {
                const int gn = n0 + wn + nf * 8 + tg * 2;
                float v0 = acc[mf][nf][half * 2 + 0] * alpha;
                float v1 = acc[mf][nf][half * 2 + 1] * alpha;
                if (bias) {
                    if (gn < N)     v0 += bias[gn];
                    if (gn + 1 < N) v1 += bias[gn + 1];
                }
                if (TRANS_OUT) {
                    if (gn < N)     C[(size_t)gn * ldc + gm] = v0;
                    if (gn + 1 < N) C[(size_t)(gn + 1) * ldc + gm] = v1;
                } else {
                    if (gn < N)     C[(size_t)gm * ldc + gn]     = v0;
                    if (gn + 1 < N) C[(size_t)gm * ldc + gn + 1] = v1;
                }
            }
        }
    }
}

// ---------------------------------------------------------------------------
// 2D-grid GEMM (n on x, m on y), optional causal tile skip
// ---------------------------------------------------------------------------
template <bool SPLIT, bool TRANS_OUT>
__global__ void __launch_bounds__(256, 1)
gemm_mma(const float* __restrict__ A, const float* __restrict__ B,
         const float* __restrict__ bias, float* __restrict__ C,
         int M, int N, int K, float alpha, int ldc, int causal)
{
    extern __shared__ float smem[];
    const int m0 = blockIdx.y * 128;
    const int n0 = blockIdx.x * 128;
    if (causal && n0 > m0 + 127) return;
    gemm_body<SPLIT, TRANS_OUT>(A, B, bias, C, M, N, K, alpha, ldc, m0, n0, smem);
}

// ---------------------------------------------------------------------------
// Grouped-swizzle GEMM (1D grid): groups of GROUP_M m-blocks, n fastest inside
// a group -> bounded B-tile reuse through L2 + clustered writes.
// occupancy 2 (regs<=128): 1-pass only.
// ---------------------------------------------------------------------------
template <bool SPLIT, int GROUP_M>
__global__ void __launch_bounds__(256, 2)
gemm_mma_grouped(const float* __restrict__ A, const float* __restrict__ B,
                 const float* __restrict__ bias, float* __restrict__ C,
                 int M, int N, int K, float alpha, int ldc)
{
    extern __shared__ float smem[];
    const int nbm = M / 128;
    const int nbn = (N + 127) / 128;
    const int bid = blockIdx.x;

    const int per_group  = GROUP_M * nbn;
    const int group      = bid / per_group;
    const int in_group   = bid % per_group;
    const int gm_blocks  = min(GROUP_M, nbm - group * GROUP_M);
    const int bm         = group * GROUP_M + in_group % gm_blocks;
    const int bn         = in_group / gm_blocks;

    gemm_body<SPLIT, false>(A, B, bias, C, M, N, K, alpha, ldc,
                            bm * 128, bn * 128, smem);
}

// ---------------------------------------------------------------------------
// Embedding gather
// ---------------------------------------------------------------------------
__global__ void gather_kernel(const int* __restrict__ tokens,
                              const float* __restrict__ E,
                              float* __restrict__ x) {
    int row = blockIdx.x;
    int t = tokens[row];
    const float4* src = reinterpret_cast<const float4*>(E + (size_t)t * DMODEL);
    float4* dst = reinterpret_cast<float4*>(x + (size_t)row * DMODEL);
    dst[threadIdx.x] = src[threadIdx.x];
}

// ---------------------------------------------------------------------------
// Causal row softmax in place
// ---------------------------------------------------------------------------
__global__ void softmax_causal_kernel(float* __restrict__ S) {
    const int row = blockIdx.x;
    float* s = S + (size_t)row * NTOK;
    const int len = row + 1;
    __shared__ float red[256];
    const int t = threadIdx.x;

    float m = -1e30f;
    for (int j = t; j < len; j += 256) m = fmaxf(m, s[j]);
    red[t] = m;
    __syncthreads();
#pragma unroll
    for (int st = 128; st > 0; st >>= 1) {
        if (t < st) red[t] = fmaxf(red[t], red[t + st]);
        __syncthreads();
    }
    m = red[0];
    __syncthreads();

    float sum = 0.0f;
    for (int j = t; j < len; j += 256) {
        const float e = expf(s[j] - m);
        s[j] = e;
        sum += e;
    }
    red[t] = sum;
    __syncthreads();
#pragma unroll
    for (int st = 128; st > 0; st >>= 1) {
        if (t < st) red[t] += red[t + st];
        __syncthreads();
    }
    const float inv = 1.0f / red[0];
    __syncthreads();

    for (int j = t; j < len; j += 256) s[j] *= inv;
    for (int j = len + t; j < NTOK; j += 256) s[j] = 0.0f;   // dense-GEMM tail
}

// ---------------------------------------------------------------------------
// Launch
// ---------------------------------------------------------------------------
extern "C" void kernel_launch(void* const* d_in, const int* in_sizes, int n_in,
                              void* d_out, int out_size) {
    const int*   tokens = (const int*)d_in[0];
    const float* E  = (const float*)d_in[1];
    const float* Wq = (const float*)d_in[2];
    const float* bq = (const float*)d_in[3];
    const float* Wk = (const float*)d_in[4];
    const float* bk = (const float*)d_in[5];
    const float* Wv = (const float*)d_in[6];
    const float* bv = (const float*)d_in[7];
    const float* Wp = (const float*)d_in[8];
    const float* bp = (const float*)d_in[9];
    float* out = (float*)d_out;

    float *x, *q, *k, *vt, *s, *o;
    cudaGetSymbolAddress((void**)&x,  g_x);
    cudaGetSymbolAddress((void**)&q,  g_q);
    cudaGetSymbolAddress((void**)&k,  g_k);
    cudaGetSymbolAddress((void**)&vt, g_vt);
    cudaGetSymbolAddress((void**)&s,  g_s);
    cudaGetSymbolAddress((void**)&o,  g_o);

    constexpr int SMEM_SPLIT = 2 * 4 * 128 * 20 * 4;   // 81920 B
    constexpr int SMEM_1P    = 2 * 2 * 128 * 20 * 4;   // 40960 B
    cudaFuncSetAttribute(gemm_mma<true, false>, cudaFuncAttributeMaxDynamicSharedMemorySize, SMEM_SPLIT);
    cudaFuncSetAttribute(gemm_mma<true, true >, cudaFuncAttributeMaxDynamicSharedMemorySize, SMEM_SPLIT);
    cudaFuncSetAttribute(gemm_mma_grouped<false, 16>, cudaFuncAttributeMaxDynamicSharedMemorySize, SMEM_1P);

    const float inv_sqrt_d = 1.0f / 32.0f;

    gather_kernel<<<NTOK, 256>>>(tokens, E, x);

    // Q/K = x @ W^T + b ; V written transposed for the AV GEMM
    dim3 g1(DMODEL / 128, NTOK / 128);
    gemm_mma<true, false><<<g1, 256, SMEM_SPLIT>>>(x, Wq, bq, q,  NTOK, DMODEL, DMODEL, 1.0f, DMODEL, 0);
    gemm_mma<true, false><<<g1, 256, SMEM_SPLIT>>>(x, Wk, bk, k,  NTOK, DMODEL, DMODEL, 1.0f, DMODEL, 0);
    gemm_mma<true, true ><<<g1, 256, SMEM_SPLIT>>>(x, Wv, bv, vt, NTOK, DMODEL, DMODEL, 1.0f, NTOK,   0);

    // S = Q @ K^T / sqrt(d)  (skip fully-masked tiles)
    dim3 g2(NTOK / 128, NTOK / 128);
    gemm_mma<true, false><<<g2, 256, SMEM_SPLIT>>>(q, k, nullptr, s, NTOK, NTOK, DMODEL, inv_sqrt_d, NTOK, 1);

    softmax_causal_kernel<<<NTOK, 256>>>(s);

    // O = A @ V  (B = V^T, K-major)
    gemm_mma<true, false><<<g1, 256, SMEM_SPLIT>>>(s, vt, nullptr, o, NTOK, DMODEL, NTOK, 1.0f, DMODEL, 0);

    // logits = O @ Wp^T + bp  (1-pass rna-tf32, grouped swizzle GROUP_M=16, occ=2)
    const int nbm = NTOK / 128;                 // 32
    const int nbn = (VOCAB + 127) / 128;        // 393
    gemm_mma_grouped<false, 16><<<nbm * nbn, 256, SMEM_1P>>>(
        o, Wp, bp, out, NTOK, VOCAB, DMODEL, 1.0f, VOCAB);
}